// round 13
// baseline (speedup 1.0000x reference)
#include <cuda_runtime.h>
#include <cuda_bf16.h>
#include <math.h>
#include <stdint.h>

// ---------------- problem constants ----------------
#define T_FR   8
#define N_TOK  257
#define HW     16
#define BATCH  8
#define D_MOD  768
#define DH     192
#define HEADS  4
#define HDIM   48
#define M_ALL  (T_FR * BATCH * N_TOK)   // 16448
#define M_PAT  (BATCH * T_FR * HW * HW) // 16384
#define KCUBE  27

// ---------------- scratch ----------------
__device__ float g_t1 [M_ALL * DH];
__device__ float g_xs [M_ALL * DH];

__device__ __nv_bfloat16 g_xb  [M_ALL * D_MOD];
__device__ __nv_bfloat16 g_t1b [M_ALL * DH];
__device__ __nv_bfloat16 g_xsb [M_ALL * DH];
__device__ __nv_bfloat16 g_yb  [M_PAT * DH];
__device__ __nv_bfloat16 g_qkvb[M_PAT * 3 * DH];
__device__ __nv_bfloat16 g_attb[M_PAT * DH];

__device__ __nv_bfloat16 g_w_fc1 [DH * D_MOD];
__device__ __nv_bfloat16 g_w_conv[DH * DH];
__device__ float         g_b_conv[DH];
__device__ __nv_bfloat16 g_w_qkv [3 * DH * DH];
__device__ __nv_bfloat16 g_w_proj[DH * DH];
__device__ __nv_bfloat16 g_w_fc2 [D_MOD * DH];

// ---------------- helpers ----------------
__device__ __forceinline__ float gelu_exact(float v) {
    return 0.5f * v * (1.0f + erff(v * 0.70710678118654752f));
}

__device__ __forceinline__ int patch_to_xs_row(int pr) {
    int b = pr >> 11;
    int t = (pr >> 8) & 7;
    int h = (pr >> 4) & 15;
    int w = pr & 15;
    return t * (BATCH * N_TOK) + b * N_TOK + 1 + (h << 4) + w;
}

__device__ __forceinline__ uint32_t pack_bf2(float lo, float hi) {
    uint32_t r;
    asm("cvt.rn.bf16x2.f32 %0, %1, %2;" : "=r"(r) : "f"(hi), "f"(lo));
    return r;
}

__device__ __forceinline__ uint32_t smem_u32(const void* p) {
    uint32_t a;
    asm("{ .reg .u64 t; cvta.to.shared.u64 t, %1; cvt.u32.u64 %0, t; }"
        : "=r"(a) : "l"(p));
    return a;
}

#define CP16(dst, src) \
    asm volatile("cp.async.cg.shared.global [%0], [%1], 16;" \
        :: "r"(dst), "l"(src) : "memory")
#define CP_COMMIT() asm volatile("cp.async.commit_group;" ::: "memory")
#define CP_WAIT(N)  asm volatile("cp.async.wait_group %0;" :: "n"(N) : "memory")

#define LDSM4(r0, r1, r2, r3, addr) \
    asm volatile("ldmatrix.sync.aligned.m8n8.x4.shared.b16 {%0,%1,%2,%3}, [%4];" \
        : "=r"(r0), "=r"(r1), "=r"(r2), "=r"(r3) : "r"(addr))

#define MMA16816(cc, A0, A1, A2, A3, B0, B1) \
    asm volatile("mma.sync.aligned.m16n8k16.row.col.f32.bf16.bf16.f32 " \
        "{%0,%1,%2,%3}, {%4,%5,%6,%7}, {%8,%9}, {%0,%1,%2,%3};" \
        : "+f"((cc)[0]), "+f"((cc)[1]), "+f"((cc)[2]), "+f"((cc)[3]) \
        : "r"(A0), "r"(A1), "r"(A2), "r"(A3), "r"(B0), "r"(B1))

// shared epilogue (pipelined kernel)
template <int MODE, bool WF32, bool WBF16>
__device__ __forceinline__ void gemm_epilogue(
    float acc[2][4][4], const float* __restrict__ bias,
    float* __restrict__ Cf, __nv_bfloat16* __restrict__ Cb,
    const float* __restrict__ res,
    int m0, int n0, int wm, int wn, int lane, int M, int N)
{
    const int r  = lane >> 2;
    const int c2 = (lane & 3) * 2;
    #pragma unroll
    for (int mi = 0; mi < 2; mi++) {
        #pragma unroll
        for (int half = 0; half < 2; half++) {
            const int m = m0 + wm + mi * 16 + r + half * 8;
            if (m >= M) continue;
            const int orow = (MODE == 2) ? patch_to_xs_row(m) : m;
            #pragma unroll
            for (int nj = 0; nj < 4; nj++) {
                const int n = n0 + wn + nj * 8 + c2;
                float v0 = acc[mi][nj][half * 2 + 0] + bias[n];
                float v1 = acc[mi][nj][half * 2 + 1] + bias[n + 1];
                if (MODE == 1) {
                    const float2 rv = *(const float2*)(res + (size_t)m * N + n);
                    v0 = gelu_exact(rv.x + v0);
                    v1 = gelu_exact(rv.y + v1);
                } else if (MODE == 2) {
                    const float2 rv = *(const float2*)(res + (size_t)orow * N + n);
                    v0 += rv.x; v1 += rv.y;
                } else if (MODE == 3) {
                    const float2 rv = *(const float2*)(res + (size_t)m * N + n);
                    v0 += rv.x; v1 += rv.y;
                }
                if (WF32) {
                    float2 o; o.x = v0; o.y = v1;
                    *(float2*)(Cf + (size_t)orow * N + n) = o;
                }
                if (WBF16) {
                    *(uint32_t*)(Cb + (size_t)orow * N + n) = pack_bf2(v0, v1);
                }
            }
        }
    }
}

// ---------------- pipelined bf16 GEMM (fc1/qkv/fc2) ----------------
#define ASTRIDE 80
#define A_ST (128 * ASTRIDE)
#define B_ST (64 * ASTRIDE)
#define STAGE (A_ST + B_ST)
#define NSTG 3

template <int MODE, bool WF32, bool WBF16>
__global__ __launch_bounds__(256)
void tc_gemm(const __nv_bfloat16* __restrict__ A,
             const __nv_bfloat16* __restrict__ W,
             const float* __restrict__ bias,
             float* __restrict__ Cf,
             __nv_bfloat16* __restrict__ Cb,
             int M, int N, int Kc,
             const float* __restrict__ res)
{
    __shared__ __align__(128) uint8_t smem[NSTG * STAGE];

    const int tid    = threadIdx.x;
    const int warpid = tid >> 5;
    const int lane   = tid & 31;
    const int m0     = blockIdx.y * 128;
    const int n0     = blockIdx.x * 64;

    const int wm = (warpid >> 1) * 32;
    const int wn = (warpid & 1) * 32;

    const uint32_t sbase = smem_u32(smem);

    const int r4 = tid >> 2;
    const int c4 = tid & 3;
    const int rowA0 = min(m0 + r4, M - 1);
    const int rowA1 = min(m0 + 64 + r4, M - 1);
    const __nv_bfloat16* Ap0 = A + (size_t)rowA0 * Kc + c4 * 8;
    const __nv_bfloat16* Ap1 = A + (size_t)rowA1 * Kc + c4 * 8;
    const __nv_bfloat16* Bp  = W + (size_t)(n0 + r4) * Kc + c4 * 8;
    const uint32_t dA0 = (uint32_t)(r4 * ASTRIDE + c4 * 16);
    const uint32_t dA1 = (uint32_t)((64 + r4) * ASTRIDE + c4 * 16);
    const uint32_t dB  = (uint32_t)(A_ST + r4 * ASTRIDE + c4 * 16);

    const int l8  = lane & 7;
    const int mtx = lane >> 3;
    const uint32_t aoff = (uint32_t)((wm + (mtx & 1) * 8 + l8) * ASTRIDE + (mtx >> 1) * 16);
    const uint32_t boff = (uint32_t)(A_ST + (wn + (mtx >> 1) * 8 + l8) * ASTRIDE + (mtx & 1) * 16);

    float acc[2][4][4];
    #pragma unroll
    for (int i = 0; i < 2; i++)
        #pragma unroll
        for (int j = 0; j < 4; j++)
            #pragma unroll
            for (int q = 0; q < 4; q++) acc[i][j][q] = 0.f;

    const int KT = Kc / 32;

    #pragma unroll
    for (int s = 0; s < 2; s++) {
        if (s < KT) {
            uint32_t b = sbase + s * STAGE;
            const int ko = s * 32;
            CP16(b + dA0, Ap0 + ko);
            CP16(b + dA1, Ap1 + ko);
            CP16(b + dB,  Bp  + ko);
            CP_COMMIT();
        }
    }

    int buf = 0;
    for (int kt = 0; kt < KT; kt++) {
        if (kt + 1 < KT) { CP_WAIT(1); } else { CP_WAIT(0); }
        __syncthreads();

        if (kt + 2 < KT) {
            int nb = buf + 2; if (nb >= NSTG) nb -= NSTG;
            uint32_t b = sbase + nb * STAGE;
            const int ko = (kt + 2) * 32;
            CP16(b + dA0, Ap0 + ko);
            CP16(b + dA1, Ap1 + ko);
            CP16(b + dB,  Bp  + ko);
            CP_COMMIT();
        }

        const uint32_t abase = sbase + buf * STAGE + aoff;
        const uint32_t bbase = sbase + buf * STAGE + boff;

        #pragma unroll
        for (int ks = 0; ks < 2; ks++) {
            uint32_t a0[4], a1[4], b0[4], b1[4];
            LDSM4(a0[0], a0[1], a0[2], a0[3], abase + ks * 32);
            LDSM4(a1[0], a1[1], a1[2], a1[3], abase + 16 * ASTRIDE + ks * 32);
            LDSM4(b0[0], b0[1], b0[2], b0[3], bbase + ks * 32);
            LDSM4(b1[0], b1[1], b1[2], b1[3], bbase + 16 * ASTRIDE + ks * 32);

            MMA16816(acc[0][0], a0[0], a0[1], a0[2], a0[3], b0[0], b0[1]);
            MMA16816(acc[0][1], a0[0], a0[1], a0[2], a0[3], b0[2], b0[3]);
            MMA16816(acc[0][2], a0[0], a0[1], a0[2], a0[3], b1[0], b1[1]);
            MMA16816(acc[0][3], a0[0], a0[1], a0[2], a0[3], b1[2], b1[3]);
            MMA16816(acc[1][0], a1[0], a1[1], a1[2], a1[3], b0[0], b0[1]);
            MMA16816(acc[1][1], a1[0], a1[1], a1[2], a1[3], b0[2], b0[3]);
            MMA16816(acc[1][2], a1[0], a1[1], a1[2], a1[3], b1[0], b1[1]);
            MMA16816(acc[1][3], a1[0], a1[1], a1[2], a1[3], b1[2], b1[3]);
        }

        if (++buf == NSTG) buf = 0;
    }

    gemm_epilogue<MODE, WF32, WBF16>(acc, bias, Cf, Cb, res, m0, n0, wm, wn, lane, M, N);
}

// ---------------- BN=192 single-shot K=192 GEMM (whole rows per block) ----------------
// MODE 1: conv+gelu+LN fused: xs=f32 gelu, xsb=bf16, yb=LN (patch rows)
// MODE 2: proj scatter: xsb[map(m)] = res[map(m)] + v
#define KSTRB 384
#define A_SZ   (128 * KSTRB)              // 49152
#define SMEM_N192 (A_SZ + 192 * KSTRB)    // 122880

template <int MODE>
__global__ __launch_bounds__(256)
void tc_gemm_n192(const __nv_bfloat16* __restrict__ A,
                  const __nv_bfloat16* __restrict__ W,
                  const float* __restrict__ bias,
                  float* __restrict__ xs,
                  __nv_bfloat16* __restrict__ xsb,
                  __nv_bfloat16* __restrict__ yb,
                  const float* __restrict__ res,
                  const float* __restrict__ gamma,
                  const float* __restrict__ beta,
                  int M)
{
    extern __shared__ __align__(128) uint8_t dsm[];

    const int tid    = threadIdx.x;
    const int warpid = tid >> 5;
    const int lane   = tid & 31;
    const int m0     = blockIdx.x * 128;

    const int wm = (warpid >> 1) * 32;    // 0,32,64,96
    const int wn = (warpid & 1) * 96;     // 0,96

    const uint32_t sbase = smem_u32(dsm);

    // stage A (128x24 chunks) + B (192x24 chunks), XOR swizzle
    #pragma unroll
    for (int i = 0; i < 12; i++) {
        const int idx = tid + 256 * i;
        const int row = idx / 24, ch = idx % 24;
        const int grow = min(m0 + row, M - 1);
        CP16(sbase + (uint32_t)(row * KSTRB + ((ch ^ (row & 7)) << 4)),
             A + (size_t)grow * DH + ch * 8);
    }
    #pragma unroll
    for (int i = 0; i < 18; i++) {
        const int idx = tid + 256 * i;
        const int row = idx / 24, ch = idx % 24;
        CP16(sbase + (uint32_t)(A_SZ + row * KSTRB + ((ch ^ (row & 7)) << 4)),
             W + (size_t)row * DH + ch * 8);
    }
    CP_COMMIT();

    const int l8  = lane & 7;
    const int mtx = lane >> 3;
    const uint32_t arow0 = sbase + (uint32_t)((wm + (mtx & 1) * 8 + l8) * KSTRB);
    const uint32_t brow0 = sbase + (uint32_t)(A_SZ + (wn + (mtx >> 1) * 8 + l8) * KSTRB);
    const int ca = mtx >> 1;
    const int cb = mtx & 1;
    const int msk = l8;

    float acc[2][12][4];
    #pragma unroll
    for (int i = 0; i < 2; i++)
        #pragma unroll
        for (int j = 0; j < 12; j++)
            #pragma unroll
            for (int q = 0; q < 4; q++) acc[i][j][q] = 0.f;

    CP_WAIT(0);
    __syncthreads();

    #pragma unroll
    for (int ks = 0; ks < 12; ks++) {
        const uint32_t sa = (uint32_t)(((ca + 2 * ks) ^ msk) << 4);
        const uint32_t sb = (uint32_t)(((cb + 2 * ks) ^ msk) << 4);
        uint32_t a0[4], a1[4];
        LDSM4(a0[0], a0[1], a0[2], a0[3], arow0 + sa);
        LDSM4(a1[0], a1[1], a1[2], a1[3], arow0 + 16 * KSTRB + sa);
        #pragma unroll
        for (int g = 0; g < 6; g++) {
            uint32_t bg[4];
            LDSM4(bg[0], bg[1], bg[2], bg[3], brow0 + g * 16 * KSTRB + sb);
            MMA16816(acc[0][2 * g],     a0[0], a0[1], a0[2], a0[3], bg[0], bg[1]);
            MMA16816(acc[0][2 * g + 1], a0[0], a0[1], a0[2], a0[3], bg[2], bg[3]);
            MMA16816(acc[1][2 * g],     a1[0], a1[1], a1[2], a1[3], bg[0], bg[1]);
            MMA16816(acc[1][2 * g + 1], a1[0], a1[1], a1[2], a1[3], bg[2], bg[3]);
        }
    }

    const int r  = lane >> 2;
    const int c2 = (lane & 3) * 2;

    if (MODE == 2) {
        // proj scatter epilogue (M == M_PAT exact, no guards)
        #pragma unroll
        for (int mi = 0; mi < 2; mi++) {
            #pragma unroll
            for (int half = 0; half < 2; half++) {
                const int m = m0 + wm + mi * 16 + r + half * 8;
                const int orow = patch_to_xs_row(m);
                #pragma unroll
                for (int nj = 0; nj < 12; nj++) {
                    const int n = wn + nj * 8 + c2;
                    float v0 = acc[mi][nj][half * 2 + 0] + bias[n];
                    float v1 = acc[mi][nj][half * 2 + 1] + bias[n + 1];
                    const float2 rv = *(const float2*)(res + (size_t)orow * DH + n);
                    *(uint32_t*)(xsb + (size_t)orow * DH + n) = pack_bf2(v0 + rv.x, v1 + rv.y);
                }
            }
        }
        return;
    }

    // ---- MODE 1: conv + gelu + LN fused ----
    __syncthreads();                 // operand smem now reusable
    float* s_sum = (float*)dsm;      // [2][128]
    float* s_sq  = (float*)dsm + 256;
    const int wnId = warpid & 1;

    // pass 1: v = gelu(res + acc + bias); write xs/xsb; partial row sums
    #pragma unroll
    for (int mi = 0; mi < 2; mi++) {
        #pragma unroll
        for (int half = 0; half < 2; half++) {
            const int m  = m0 + wm + mi * 16 + r + half * 8;
            const bool ok = (m < M);
            float psum = 0.f;
            #pragma unroll
            for (int nj = 0; nj < 12; nj++) {
                const int n = wn + nj * 8 + c2;
                float v0 = acc[mi][nj][half * 2 + 0] + bias[n];
                float v1 = acc[mi][nj][half * 2 + 1] + bias[n + 1];
                if (ok) {
                    const float2 rv = *(const float2*)(res + (size_t)m * DH + n);
                    v0 = gelu_exact(rv.x + v0);
                    v1 = gelu_exact(rv.y + v1);
                    float2 o; o.x = v0; o.y = v1;
                    *(float2*)(xs + (size_t)m * DH + n) = o;
                    *(uint32_t*)(xsb + (size_t)m * DH + n) = pack_bf2(v0, v1);
                }
                acc[mi][nj][half * 2 + 0] = v0;
                acc[mi][nj][half * 2 + 1] = v1;
                psum += v0 + v1;
            }
            psum += __shfl_xor_sync(0xffffffff, psum, 1);
            psum += __shfl_xor_sync(0xffffffff, psum, 2);
            if ((lane & 3) == 0)
                s_sum[wnId * 128 + wm + mi * 16 + half * 8 + r] = psum;
        }
    }
    __syncthreads();

    // pass 2: variance partials about the true mean
    #pragma unroll
    for (int mi = 0; mi < 2; mi++) {
        #pragma unroll
        for (int half = 0; half < 2; half++) {
            const int rowL = wm + mi * 16 + half * 8 + r;
            const float mu = (s_sum[rowL] + s_sum[128 + rowL]) * (1.0f / DH);
            float psq = 0.f;
            #pragma unroll
            for (int nj = 0; nj < 12; nj++) {
                float d0 = acc[mi][nj][half * 2 + 0] - mu;
                float d1 = acc[mi][nj][half * 2 + 1] - mu;
                psq += d0 * d0 + d1 * d1;
            }
            psq += __shfl_xor_sync(0xffffffff, psq, 1);
            psq += __shfl_xor_sync(0xffffffff, psq, 2);
            if ((lane & 3) == 0)
                s_sq[wnId * 128 + rowL] = psq;
        }
    }
    __syncthreads();

    // pass 3: LN output for patch rows
    #pragma unroll
    for (int mi = 0; mi < 2; mi++) {
        #pragma unroll
        for (int half = 0; half < 2; half++) {
            const int rowL = wm + mi * 16 + half * 8 + r;
            const int m = m0 + rowL;
            if (m >= M) continue;
            const int t   = m / (BATCH * N_TOK);
            const int rem = m - t * (BATCH * N_TOK);
            const int bq  = rem / N_TOK;
            const int nn  = rem - bq * N_TOK;
            if (nn == 0) continue;                 // cls token
            const int pr = ((bq * T_FR + t) << 8) + (nn - 1);
            const float mu  = (s_sum[rowL] + s_sum[128 + rowL]) * (1.0f / DH);
            const float var = (s_sq[rowL] + s_sq[128 + rowL]) * (1.0f / DH);
            const float inv = rsqrtf(var + 1e-5f);
            #pragma unroll
            for (int nj = 0; nj < 12; nj++) {
                const int n = wn + nj * 8 + c2;
                const float2 gv = *(const float2*)(gamma + n);
                const float2 bv = *(const float2*)(beta + n);
                float y0 = (acc[mi][nj][half * 2 + 0] - mu) * inv * gv.x + bv.x;
                float y1 = (acc[mi][nj][half * 2 + 1] - mu) * inv * gv.y + bv.y;
                *(uint32_t*)(yb + (size_t)pr * DH + n) = pack_bf2(y0, y1);
            }
        }
    }
}

// ---------------- prep: x->bf16 + weight conversions + conv fold ----------------
__global__ void prep_kernel(const float* __restrict__ x,
                            const float* s0, const float* s3,
                            const float* s4, const float* s5,
                            const float* cA, const float* cAb,
                            const float* cB, const float* cBb)
{
    const int stride = gridDim.x * blockDim.x;
    const int t = blockIdx.x * blockDim.x + threadIdx.x;

    const int n4 = (M_ALL * D_MOD) / 4;
    for (int i = t; i < n4; i += stride) {
        float4 v = *(const float4*)(x + 4 * (size_t)i);
        uint2 o;
        o.x = pack_bf2(v.x, v.y);
        o.y = pack_bf2(v.z, v.w);
        *(uint2*)((uint16_t*)g_xb + 4 * (size_t)i) = o;
    }

    for (int i = t; i < DH * D_MOD;   i += stride) g_w_fc1[i]  = __float2bfloat16(s0[i]);
    for (int i = t; i < 3 * DH * DH;  i += stride) g_w_qkv[i]  = __float2bfloat16(s3[i]);
    for (int i = t; i < DH * DH;      i += stride) g_w_proj[i] = __float2bfloat16(s4[i]);
    for (int i = t; i < D_MOD * DH;   i += stride) g_w_fc2[i]  = __float2bfloat16(s5[i]);
    for (int idx = t; idx < DH * DH; idx += stride) {
        const int i = idx / DH, j = idx % DH;
        float s = 0.f;
        #pragma unroll 8
        for (int k = 0; k < 64; k++)
            s = fmaf(cB[i * 64 + k], cA[k * DH + j], s);
        g_w_conv[idx] = __float2bfloat16(s);
    }
    for (int i = t; i < DH; i += stride) {
        float s = cBb[i];
        for (int k = 0; k < 64; k++)
            s = fmaf(cB[i * 64 + k], cAb[k], s);
        g_b_conv[i] = s;
    }
}

// ---------------- tiled 3D neighborhood attention ----------------
#define KSTR 200
#define RMAX 108
#define OFF_K 0
#define OFF_V (RMAX * KSTR * 2)
#define OFF_Q (OFF_V + RMAX * KSTR * 2)
#define OFF_P (OFF_Q + 16 * DH * 4)
#define OFF_R (OFF_P + 16 * 108 * 4)
#define SMEM_ATT (OFF_R + 16 * 27 * 4)

__global__ __launch_bounds__(256)
void attn_tiled(const __nv_bfloat16* __restrict__ qkvb,
                const float* __restrict__ rpb,
                __nv_bfloat16* __restrict__ att)
{
    extern __shared__ __align__(16) uint8_t dyn[];
    __nv_bfloat16* s_k = (__nv_bfloat16*)(dyn + OFF_K);
    __nv_bfloat16* s_v = (__nv_bfloat16*)(dyn + OFF_V);
    float*         s_q = (float*)(dyn + OFF_Q);
    float*         s_p = (float*)(dyn + OFF_P);
    int*           s_r = (int*)(dyn + OFF_R);

    const int tid  = threadIdx.x;
    const int wid  = tid >> 5;
    const int lane = tid & 31;

    int bid = blockIdx.x;
    const int tw = bid & 3;  bid >>= 2;
    const int th = bid & 3;  bid >>= 2;
    const int t  = bid & 7;  bid >>= 3;
    const int b  = bid;
    const int h0 = th * 4, w0 = tw * 4;

    const int st  = min(max(t - 1, 0), T_FR - 3);
    const int hU0 = max(h0 - 1, 0), hU1 = min(h0 + 4, 15);
    const int wU0 = max(w0 - 1, 0), wU1 = min(w0 + 4, 15);
    const int nH  = hU1 - hU0 + 1;
    const int nW  = wU1 - wU0 + 1;
    const int R   = 3 * nH * nW;

    for (int r = wid; r < R; r += 8) {
        const int f   = r / (nH * nW);
        const int rem = r - f * (nH * nW);
        const int hh  = hU0 + rem / nW;
        const int ww  = wU0 + rem % nW;
        const int grow = ((b * T_FR + st + f) * HW + hh) * HW + ww;
        const uint4* src = (const uint4*)(qkvb + (size_t)grow * (3 * DH) + DH);
        uint4* dk = (uint4*)(s_k + r * KSTR);
        uint4* dv = (uint4*)(s_v + r * KSTR);
        {
            const int ch = lane;
            if (ch < 24) dk[ch] = src[ch];
            else         dv[ch - 24] = src[ch];
        }
        if (lane < 16) {
            const int ch = lane + 32;
            dv[ch - 24] = src[ch];
        }
    }

    const float scale = 0.144337567297406f;
    for (int idx = tid; idx < 16 * DH; idx += 256) {
        const int i = idx / DH, c = idx - i * DH;
        const int hh = h0 + (i >> 2), ww = w0 + (i & 3);
        const int grow = ((b * T_FR + t) * HW + hh) * HW + ww;
        s_q[idx] = __bfloat162float(qkvb[(size_t)grow * (3 * DH) + c]) * scale;
    }

    for (int idx = tid; idx < 16 * KCUBE; idx += 256) {
        const int i = idx / KCUBE, nb = idx - i * KCUBE;
        const int kt = nb / 9, kh = (nb / 3) % 3, kw = nb % 3;
        const int hh = h0 + (i >> 2), ww = w0 + (i & 3);
        const int sh = min(max(hh - 1, 0), HW - 3);
        const int sw = min(max(ww - 1, 0), HW - 3);
        s_r[idx] = (kt * nH + (sh + kh - hU0)) * nW + (sw + kw - wU0);
    }
    __syncthreads();

    for (int idx = tid; idx < 16 * 108; idx += 256) {
        const int i   = idx / 108;
        const int rem = idx - i * 108;
        const int head = rem / KCUBE, nb = rem - head * KCUBE;
        const int r = s_r[i * KCUBE + nb];
        const __nv_bfloat16* kp = s_k + r * KSTR + head * HDIM;
        const float* qp = s_q + i * DH + head * HDIM;
        float s = 0.f;
        #pragma unroll
        for (int j = 0; j < HDIM; j++)
            s = fmaf(qp[j], __bfloat162float(kp[j]), s);
        const int kt = nb / 9, kh = (nb / 3) % 3, kw = nb % 3;
        const int hh = h0 + (i >> 2), ww = w0 + (i & 3);
        const int sh = min(max(hh - 1, 0), HW - 3);
        const int sw = min(max(ww - 1, 0), HW - 3);
        const int rt = st + kt - t + 2;
        const int rh = sh + kh - hh + 2;
        const int rw = sw + kw - ww + 2;
        s += rpb[((head * 5 + rt) * 5 + rh) * 5 + rw];
        s_p[idx] = s;
    }
    __syncthreads();

    if (tid < 64) {
        const int i = tid >> 2, head = tid & 3;
        float* pp = s_p + i * 108 + head * KCUBE;
        float mx = -1e30f;
        #pragma unroll
        for (int k = 0; k < KCUBE; k++) mx = fmaxf(mx, pp[k]);
        float sum = 0.f;
        #pragma unroll
        for (int k = 0; k < KCUBE; k++) { float e = __expf(pp[k] - mx); pp[k] = e; sum += e; }
        const float inv = 1.0f / sum;
        #pragma unroll
        for (int k = 0; k < KCUBE; k++) pp[k] *= inv;
    }
    __syncthreads();

    for (int idx = tid; idx < 16 * DH; idx += 256) {
        const int i = idx / DH, c = idx - i * DH;
        const int head = c / HDIM;
        const float* pp = s_p + i * 108 + head * KCUBE;
        const int*   rt = s_r + i * KCUBE;
        float o = 0.f;
        #pragma unroll
        for (int nb = 0; nb < KCUBE; nb++)
            o = fmaf(pp[nb], __bfloat162float(s_v[rt[nb] * KSTR + c]), o);
        const int hh = h0 + (i >> 2), ww = w0 + (i & 3);
        const int grow = ((b * T_FR + t) * HW + hh) * HW + ww;
        att[(size_t)grow * DH + c] = __float2bfloat16(o);
    }
}

// ---------------- launch ----------------
extern "C" void kernel_launch(void* const* d_in, const int* in_sizes, int n_in,
                              void* d_out, int out_size)
{
    const float* x       = (const float*)d_in[0];
    const float* fc1_w   = (const float*)d_in[1];
    const float* fc1_b   = (const float*)d_in[2];
    const float* convA_w = (const float*)d_in[3];
    const float* convA_b = (const float*)d_in[4];
    const float* convB_w = (const float*)d_in[5];
    const float* convB_b = (const float*)d_in[6];
    const float* ln_g    = (const float*)d_in[7];
    const float* ln_b    = (const float*)d_in[8];
    const float* qkv_w   = (const float*)d_in[9];
    const float* qkv_b   = (const float*)d_in[10];
    const float* rpb     = (const float*)d_in[11];
    const float* proj_w  = (const float*)d_in[12];
    const float* proj_b  = (const float*)d_in[13];
    const float* fc2_w   = (const float*)d_in[14];
    const float* fc2_b   = (const float*)d_in[15];
    float* out = (float*)d_out;

    float *t1, *xs, *bconv;
    __nv_bfloat16 *xb, *t1b, *xsb, *yb, *qkvb, *attb;
    __nv_bfloat16 *wfc1, *wconv, *wqkv, *wproj, *wfc2;
    cudaGetSymbolAddress((void**)&t1,    g_t1);
    cudaGetSymbolAddress((void**)&xs,    g_xs);
    cudaGetSymbolAddress((void**)&bconv, g_b_conv);
    cudaGetSymbolAddress((void**)&xb,    g_xb);
    cudaGetSymbolAddress((void**)&t1b,   g_t1b);
    cudaGetSymbolAddress((void**)&xsb,   g_xsb);
    cudaGetSymbolAddress((void**)&yb,    g_yb);
    cudaGetSymbolAddress((void**)&qkvb,  g_qkvb);
    cudaGetSymbolAddress((void**)&attb,  g_attb);
    cudaGetSymbolAddress((void**)&wfc1,  g_w_fc1);
    cudaGetSymbolAddress((void**)&wconv, g_w_conv);
    cudaGetSymbolAddress((void**)&wqkv,  g_w_qkv);
    cudaGetSymbolAddress((void**)&wproj, g_w_proj);
    cudaGetSymbolAddress((void**)&wfc2,  g_w_fc2);

    cudaFuncSetAttribute(attn_tiled,
                         cudaFuncAttributeMaxDynamicSharedMemorySize, SMEM_ATT);
    cudaFuncSetAttribute(tc_gemm_n192<1>,
                         cudaFuncAttributeMaxDynamicSharedMemorySize, SMEM_N192);
    cudaFuncSetAttribute(tc_gemm_n192<2>,
                         cudaFuncAttributeMaxDynamicSharedMemorySize, SMEM_N192);

    const int gyA = (M_ALL + 127) / 128;   // 129
    const int gyP = M_PAT / 128;           // 128

    // 0) x conversion + weight prep
    prep_kernel<<<1024, 256>>>(x, fc1_w, qkv_w, proj_w, fc2_w,
                               convA_w, convA_b, convB_w, convB_b);
    // 1) fc1 (K=768, pipelined) -> t1 (f32) + t1b (bf16)
    tc_gemm<0, true, true><<<dim3(3, gyA), 256>>>(xb, wfc1, fc1_b, t1, t1b,
                                                  M_ALL, DH, D_MOD, nullptr);
    // 2) fused conv+gelu+LN (BN=192 single-shot) -> xs, xsb, yb
    tc_gemm_n192<1><<<gyA, 256, SMEM_N192>>>(t1b, wconv, bconv,
                                             xs, xsb, yb, t1, ln_g, ln_b, M_ALL);
    // 3) qkv (K=192, pipelined) -> qkvb
    tc_gemm<0, false, true><<<dim3(9, gyP), 256>>>(yb, wqkv, qkv_b, nullptr, qkvb,
                                                   M_PAT, 3 * DH, DH, nullptr);
    // 4) tiled attention -> attb (bf16)
    attn_tiled<<<BATCH * T_FR * 16, 256, SMEM_ATT>>>(qkvb, rpb, attb);
    // 5) proj (BN=192 single-shot): xsb[rr] = xs[rr] + proj(attb) + b
    tc_gemm_n192<2><<<gyP, 256, SMEM_N192>>>(attb, wproj, proj_b,
                                             nullptr, xsb, nullptr, xs,
                                             nullptr, nullptr, M_PAT);
    // 6) fc2 (K=192, pipelined) + outer residual(x) -> out (f32)
    tc_gemm<3, true, false><<<dim3(12, gyA), 256>>>(xsb, wfc2, fc2_b, out, nullptr,
                                                    M_ALL, D_MOD, DH, x);
}

// round 15
// speedup vs baseline: 1.0479x; 1.0479x over previous
#include <cuda_runtime.h>
#include <cuda_bf16.h>
#include <math.h>
#include <stdint.h>

// ---------------- problem constants ----------------
#define T_FR   8
#define N_TOK  257
#define HW     16
#define BATCH  8
#define D_MOD  768
#define DH     192
#define HEADS  4
#define HDIM   48
#define M_ALL  (T_FR * BATCH * N_TOK)   // 16448
#define M_PAT  (BATCH * T_FR * HW * HW) // 16384
#define KCUBE  27

// ---------------- scratch ----------------
__device__ float g_t1 [M_ALL * DH];
__device__ float g_xs [M_ALL * DH];

__device__ __nv_bfloat16 g_xb  [M_ALL * D_MOD];
__device__ __nv_bfloat16 g_t1b [M_ALL * DH];
__device__ __nv_bfloat16 g_xsb [M_ALL * DH];
__device__ __nv_bfloat16 g_yb  [M_PAT * DH];
__device__ __nv_bfloat16 g_qkvb[M_PAT * 3 * DH];
__device__ __nv_bfloat16 g_attb[M_PAT * DH];

__device__ __nv_bfloat16 g_w_fc1 [DH * D_MOD];
__device__ __nv_bfloat16 g_w_conv[DH * DH];
__device__ float         g_b_conv[DH];
__device__ __nv_bfloat16 g_w_qkv [3 * DH * DH];
__device__ __nv_bfloat16 g_w_proj[DH * DH];
__device__ __nv_bfloat16 g_w_fc2 [D_MOD * DH];

// ---------------- helpers ----------------
__device__ __forceinline__ float gelu_exact(float v) {
    return 0.5f * v * (1.0f + erff(v * 0.70710678118654752f));
}

__device__ __forceinline__ int patch_to_xs_row(int pr) {
    int b = pr >> 11;
    int t = (pr >> 8) & 7;
    int h = (pr >> 4) & 15;
    int w = pr & 15;
    return t * (BATCH * N_TOK) + b * N_TOK + 1 + (h << 4) + w;
}

__device__ __forceinline__ uint32_t pack_bf2(float lo, float hi) {
    uint32_t r;
    asm("cvt.rn.bf16x2.f32 %0, %1, %2;" : "=r"(r) : "f"(hi), "f"(lo));
    return r;
}

__device__ __forceinline__ uint32_t smem_u32(const void* p) {
    uint32_t a;
    asm("{ .reg .u64 t; cvta.to.shared.u64 t, %1; cvt.u32.u64 %0, t; }"
        : "=r"(a) : "l"(p));
    return a;
}

#define CP16(dst, src) \
    asm volatile("cp.async.cg.shared.global [%0], [%1], 16;" \
        :: "r"(dst), "l"(src) : "memory")
#define CP_COMMIT() asm volatile("cp.async.commit_group;" ::: "memory")
#define CP_WAIT(N)  asm volatile("cp.async.wait_group %0;" :: "n"(N) : "memory")

#define LDSM4(r0, r1, r2, r3, addr) \
    asm volatile("ldmatrix.sync.aligned.m8n8.x4.shared.b16 {%0,%1,%2,%3}, [%4];" \
        : "=r"(r0), "=r"(r1), "=r"(r2), "=r"(r3) : "r"(addr))

#define MMA16816(cc, A0, A1, A2, A3, B0, B1) \
    asm volatile("mma.sync.aligned.m16n8k16.row.col.f32.bf16.bf16.f32 " \
        "{%0,%1,%2,%3}, {%4,%5,%6,%7}, {%8,%9}, {%0,%1,%2,%3};" \
        : "+f"((cc)[0]), "+f"((cc)[1]), "+f"((cc)[2]), "+f"((cc)[3]) \
        : "r"(A0), "r"(A1), "r"(A2), "r"(A3), "r"(B0), "r"(B1))

// shared epilogue (pipelined kernel)
template <int MODE, bool WF32, bool WBF16>
__device__ __forceinline__ void gemm_epilogue(
    float acc[2][4][4], const float* __restrict__ bias,
    float* __restrict__ Cf, __nv_bfloat16* __restrict__ Cb,
    const float* __restrict__ res,
    int m0, int n0, int wm, int wn, int lane, int M, int N)
{
    const int r  = lane >> 2;
    const int c2 = (lane & 3) * 2;
    #pragma unroll
    for (int mi = 0; mi < 2; mi++) {
        #pragma unroll
        for (int half = 0; half < 2; half++) {
            const int m = m0 + wm + mi * 16 + r + half * 8;
            if (m >= M) continue;
            const int orow = (MODE == 2) ? patch_to_xs_row(m) : m;
            #pragma unroll
            for (int nj = 0; nj < 4; nj++) {
                const int n = n0 + wn + nj * 8 + c2;
                float v0 = acc[mi][nj][half * 2 + 0] + bias[n];
                float v1 = acc[mi][nj][half * 2 + 1] + bias[n + 1];
                if (MODE == 1) {
                    const float2 rv = *(const float2*)(res + (size_t)m * N + n);
                    v0 = gelu_exact(rv.x + v0);
                    v1 = gelu_exact(rv.y + v1);
                } else if (MODE == 2) {
                    const float2 rv = *(const float2*)(res + (size_t)orow * N + n);
                    v0 += rv.x; v1 += rv.y;
                } else if (MODE == 3) {
                    const float2 rv = *(const float2*)(res + (size_t)m * N + n);
                    v0 += rv.x; v1 += rv.y;
                }
                if (WF32) {
                    float2 o; o.x = v0; o.y = v1;
                    *(float2*)(Cf + (size_t)orow * N + n) = o;
                }
                if (WBF16) {
                    *(uint32_t*)(Cb + (size_t)orow * N + n) = pack_bf2(v0, v1);
                }
            }
        }
    }
}

// ---------------- pipelined bf16 GEMM (fc1/qkv/fc2) ----------------
#define ASTRIDE 80
#define A_ST (128 * ASTRIDE)
#define B_ST (64 * ASTRIDE)
#define STAGE (A_ST + B_ST)
#define NSTG 3

template <int MODE, bool WF32, bool WBF16>
__global__ __launch_bounds__(256)
void tc_gemm(const __nv_bfloat16* __restrict__ A,
             const __nv_bfloat16* __restrict__ W,
             const float* __restrict__ bias,
             float* __restrict__ Cf,
             __nv_bfloat16* __restrict__ Cb,
             int M, int N, int Kc,
             const float* __restrict__ res)
{
    __shared__ __align__(128) uint8_t smem[NSTG * STAGE];

    const int tid    = threadIdx.x;
    const int warpid = tid >> 5;
    const int lane   = tid & 31;
    const int m0     = blockIdx.y * 128;
    const int n0     = blockIdx.x * 64;

    const int wm = (warpid >> 1) * 32;
    const int wn = (warpid & 1) * 32;

    const uint32_t sbase = smem_u32(smem);

    const int r4 = tid >> 2;
    const int c4 = tid & 3;
    const int rowA0 = min(m0 + r4, M - 1);
    const int rowA1 = min(m0 + 64 + r4, M - 1);
    const __nv_bfloat16* Ap0 = A + (size_t)rowA0 * Kc + c4 * 8;
    const __nv_bfloat16* Ap1 = A + (size_t)rowA1 * Kc + c4 * 8;
    const __nv_bfloat16* Bp  = W + (size_t)(n0 + r4) * Kc + c4 * 8;
    const uint32_t dA0 = (uint32_t)(r4 * ASTRIDE + c4 * 16);
    const uint32_t dA1 = (uint32_t)((64 + r4) * ASTRIDE + c4 * 16);
    const uint32_t dB  = (uint32_t)(A_ST + r4 * ASTRIDE + c4 * 16);

    const int l8  = lane & 7;
    const int mtx = lane >> 3;
    const uint32_t aoff = (uint32_t)((wm + (mtx & 1) * 8 + l8) * ASTRIDE + (mtx >> 1) * 16);
    const uint32_t boff = (uint32_t)(A_ST + (wn + (mtx >> 1) * 8 + l8) * ASTRIDE + (mtx & 1) * 16);

    float acc[2][4][4];
    #pragma unroll
    for (int i = 0; i < 2; i++)
        #pragma unroll
        for (int j = 0; j < 4; j++)
            #pragma unroll
            for (int q = 0; q < 4; q++) acc[i][j][q] = 0.f;

    const int KT = Kc / 32;

    #pragma unroll
    for (int s = 0; s < 2; s++) {
        if (s < KT) {
            uint32_t b = sbase + s * STAGE;
            const int ko = s * 32;
            CP16(b + dA0, Ap0 + ko);
            CP16(b + dA1, Ap1 + ko);
            CP16(b + dB,  Bp  + ko);
            CP_COMMIT();
        }
    }

    int buf = 0;
    for (int kt = 0; kt < KT; kt++) {
        if (kt + 1 < KT) { CP_WAIT(1); } else { CP_WAIT(0); }
        __syncthreads();

        if (kt + 2 < KT) {
            int nb = buf + 2; if (nb >= NSTG) nb -= NSTG;
            uint32_t b = sbase + nb * STAGE;
            const int ko = (kt + 2) * 32;
            CP16(b + dA0, Ap0 + ko);
            CP16(b + dA1, Ap1 + ko);
            CP16(b + dB,  Bp  + ko);
            CP_COMMIT();
        }

        const uint32_t abase = sbase + buf * STAGE + aoff;
        const uint32_t bbase = sbase + buf * STAGE + boff;

        #pragma unroll
        for (int ks = 0; ks < 2; ks++) {
            uint32_t a0[4], a1[4], b0[4], b1[4];
            LDSM4(a0[0], a0[1], a0[2], a0[3], abase + ks * 32);
            LDSM4(a1[0], a1[1], a1[2], a1[3], abase + 16 * ASTRIDE + ks * 32);
            LDSM4(b0[0], b0[1], b0[2], b0[3], bbase + ks * 32);
            LDSM4(b1[0], b1[1], b1[2], b1[3], bbase + 16 * ASTRIDE + ks * 32);

            MMA16816(acc[0][0], a0[0], a0[1], a0[2], a0[3], b0[0], b0[1]);
            MMA16816(acc[0][1], a0[0], a0[1], a0[2], a0[3], b0[2], b0[3]);
            MMA16816(acc[0][2], a0[0], a0[1], a0[2], a0[3], b1[0], b1[1]);
            MMA16816(acc[0][3], a0[0], a0[1], a0[2], a0[3], b1[2], b1[3]);
            MMA16816(acc[1][0], a1[0], a1[1], a1[2], a1[3], b0[0], b0[1]);
            MMA16816(acc[1][1], a1[0], a1[1], a1[2], a1[3], b0[2], b0[3]);
            MMA16816(acc[1][2], a1[0], a1[1], a1[2], a1[3], b1[0], b1[1]);
            MMA16816(acc[1][3], a1[0], a1[1], a1[2], a1[3], b1[2], b1[3]);
        }

        if (++buf == NSTG) buf = 0;
    }

    gemm_epilogue<MODE, WF32, WBF16>(acc, bias, Cf, Cb, res, m0, n0, wm, wn, lane, M, N);
}

// ---------------- single-shot K=192 GEMM, XOR-swizzled (conv/proj) ----------------
#define KSTRB 384
#define A192  (128 * KSTRB)
#define SMEM_G192 (A192 + 64 * KSTRB)    // 73728

template <int MODE, bool WF32, bool WBF16>
__global__ __launch_bounds__(256)
void tc_gemm_k192(const __nv_bfloat16* __restrict__ A,
                  const __nv_bfloat16* __restrict__ W,
                  const float* __restrict__ bias,
                  float* __restrict__ Cf,
                  __nv_bfloat16* __restrict__ Cb,
                  int M, int N,
                  const float* __restrict__ res)
{
    extern __shared__ __align__(128) uint8_t dsm[];

    const int tid    = threadIdx.x;
    const int warpid = tid >> 5;
    const int lane   = tid & 31;
    const int m0     = blockIdx.y * 128;
    const int n0     = blockIdx.x * 64;
    const int Kc     = 192;

    const int wm = (warpid >> 1) * 32;
    const int wn = (warpid & 1) * 32;

    const uint32_t sbase = smem_u32(dsm);

    #pragma unroll
    for (int i = 0; i < 12; i++) {
        const int idx = tid + 256 * i;
        const int row = idx / 24, ch = idx % 24;
        const int grow = min(m0 + row, M - 1);
        CP16(sbase + (uint32_t)(row * KSTRB + ((ch ^ (row & 7)) << 4)),
             A + (size_t)grow * Kc + ch * 8);
    }
    #pragma unroll
    for (int i = 0; i < 6; i++) {
        const int idx = tid + 256 * i;
        const int row = idx / 24, ch = idx % 24;
        CP16(sbase + (uint32_t)(A192 + row * KSTRB + ((ch ^ (row & 7)) << 4)),
             W + (size_t)(n0 + row) * Kc + ch * 8);
    }
    CP_COMMIT();

    const int l8  = lane & 7;
    const int mtx = lane >> 3;
    const uint32_t arow0 = sbase + (uint32_t)((wm + (mtx & 1) * 8 + l8) * KSTRB);
    const uint32_t brow0 = sbase + (uint32_t)(A192 + (wn + (mtx >> 1) * 8 + l8) * KSTRB);
    const int ca = mtx >> 1;
    const int cb = mtx & 1;
    const int msk = l8;

    float acc[2][4][4];
    #pragma unroll
    for (int i = 0; i < 2; i++)
        #pragma unroll
        for (int j = 0; j < 4; j++)
            #pragma unroll
            for (int q = 0; q < 4; q++) acc[i][j][q] = 0.f;

    CP_WAIT(0);
    __syncthreads();

    #pragma unroll
    for (int ks = 0; ks < 12; ks++) {
        const uint32_t sa = (uint32_t)(((ca + 2 * ks) ^ msk) << 4);
        const uint32_t sb = (uint32_t)(((cb + 2 * ks) ^ msk) << 4);
        uint32_t a0[4], a1[4], b0[4], b1[4];
        LDSM4(a0[0], a0[1], a0[2], a0[3], arow0 + sa);
        LDSM4(a1[0], a1[1], a1[2], a1[3], arow0 + 16 * KSTRB + sa);
        LDSM4(b0[0], b0[1], b0[2], b0[3], brow0 + sb);
        LDSM4(b1[0], b1[1], b1[2], b1[3], brow0 + 16 * KSTRB + sb);

        MMA16816(acc[0][0], a0[0], a0[1], a0[2], a0[3], b0[0], b0[1]);
        MMA16816(acc[0][1], a0[0], a0[1], a0[2], a0[3], b0[2], b0[3]);
        MMA16816(acc[0][2], a0[0], a0[1], a0[2], a0[3], b1[0], b1[1]);
        MMA16816(acc[0][3], a0[0], a0[1], a0[2], a0[3], b1[2], b1[3]);
        MMA16816(acc[1][0], a1[0], a1[1], a1[2], a1[3], b0[0], b0[1]);
        MMA16816(acc[1][1], a1[0], a1[1], a1[2], a1[3], b0[2], b0[3]);
        MMA16816(acc[1][2], a1[0], a1[1], a1[2], a1[3], b1[0], b1[1]);
        MMA16816(acc[1][3], a1[0], a1[1], a1[2], a1[3], b1[2], b1[3]);
    }

    gemm_epilogue<MODE, WF32, WBF16>(acc, bias, Cf, Cb, res, m0, n0, wm, wn, lane, M, N);
}

// ---------------- prep: x->bf16 + weight conversions + conv fold ----------------
__global__ void prep_kernel(const float* __restrict__ x,
                            const float* s0, const float* s3,
                            const float* s4, const float* s5,
                            const float* cA, const float* cAb,
                            const float* cB, const float* cBb)
{
    const int stride = gridDim.x * blockDim.x;
    const int t = blockIdx.x * blockDim.x + threadIdx.x;

    const int n4 = (M_ALL * D_MOD) / 4;
    for (int i = t; i < n4; i += stride) {
        float4 v = *(const float4*)(x + 4 * (size_t)i);
        uint2 o;
        o.x = pack_bf2(v.x, v.y);
        o.y = pack_bf2(v.z, v.w);
        *(uint2*)((uint16_t*)g_xb + 4 * (size_t)i) = o;
    }

    for (int i = t; i < DH * D_MOD;   i += stride) g_w_fc1[i]  = __float2bfloat16(s0[i]);
    for (int i = t; i < 3 * DH * DH;  i += stride) g_w_qkv[i]  = __float2bfloat16(s3[i]);
    for (int i = t; i < DH * DH;      i += stride) g_w_proj[i] = __float2bfloat16(s4[i]);
    for (int i = t; i < D_MOD * DH;   i += stride) g_w_fc2[i]  = __float2bfloat16(s5[i]);
    for (int idx = t; idx < DH * DH; idx += stride) {
        const int i = idx / DH, j = idx % DH;
        float s = 0.f;
        #pragma unroll 8
        for (int k = 0; k < 64; k++)
            s = fmaf(cB[i * 64 + k], cA[k * DH + j], s);
        g_w_conv[idx] = __float2bfloat16(s);
    }
    for (int i = t; i < DH; i += stride) {
        float s = cBb[i];
        for (int k = 0; k < 64; k++)
            s = fmaf(cB[i * 64 + k], cAb[k], s);
        g_b_conv[i] = s;
    }
}

// ---------------- LayerNorm: warp-per-row ----------------
__global__ __launch_bounds__(256)
void ln_warp(const float* __restrict__ xs,
             const float* __restrict__ gamma,
             const float* __restrict__ beta,
             __nv_bfloat16* __restrict__ y)
{
    const int wid  = threadIdx.x >> 5;
    const int lane = threadIdx.x & 31;
    const int pr   = blockIdx.x * 8 + wid;
    const int row  = patch_to_xs_row(pr);

    const float* src = xs + (size_t)row * DH;
    float v[6];
    float s = 0.f;
    #pragma unroll
    for (int k = 0; k < 6; k++) { v[k] = src[lane + 32 * k]; s += v[k]; }
    #pragma unroll
    for (int o = 16; o > 0; o >>= 1) s += __shfl_xor_sync(0xffffffff, s, o);
    const float mu = s * (1.0f / DH);

    float s2 = 0.f;
    #pragma unroll
    for (int k = 0; k < 6; k++) { v[k] -= mu; s2 += v[k] * v[k]; }
    #pragma unroll
    for (int o = 16; o > 0; o >>= 1) s2 += __shfl_xor_sync(0xffffffff, s2, o);
    const float inv = rsqrtf(s2 * (1.0f / DH) + 1e-5f);

    #pragma unroll
    for (int k = 0; k < 6; k++) {
        const int c = lane + 32 * k;
        y[(size_t)pr * DH + c] = __float2bfloat16(v[k] * inv * gamma[c] + beta[c]);
    }
}

// ---------------- per-(tile, head) 3D neighborhood attention ----------------
// One block = (4x4 spatial tile, 1 head). Stages only this head's 96B slice
// of each union K/V row. 31KB static smem -> ~7 blocks/SM. Grid 4096.
#define RMAX  108
#define AKSTR 56   // bf16 per row (48 + 8 pad); 112B, 16B-aligned

__global__ __launch_bounds__(256)
void attn_head(const __nv_bfloat16* __restrict__ qkvb,
               const float* __restrict__ rpb,
               __nv_bfloat16* __restrict__ att)
{
    __shared__ __nv_bfloat16 s_k[RMAX * AKSTR];
    __shared__ __nv_bfloat16 s_v[RMAX * AKSTR];
    __shared__ float s_q[16 * HDIM];
    __shared__ float s_p[16 * KCUBE];
    __shared__ int   s_r[16 * KCUBE];

    const int tid = threadIdx.x;

    int bid = blockIdx.x;
    const int head = bid & 3;  bid >>= 2;
    const int tw   = bid & 3;  bid >>= 2;
    const int th   = bid & 3;  bid >>= 2;
    const int t    = bid & 7;  bid >>= 3;
    const int b    = bid;
    const int h0 = th * 4, w0 = tw * 4;

    const int st  = min(max(t - 1, 0), T_FR - 3);
    const int hU0 = max(h0 - 1, 0), hU1 = min(h0 + 4, 15);
    const int wU0 = max(w0 - 1, 0), wU1 = min(w0 + 4, 15);
    const int nH  = hU1 - hU0 + 1;
    const int nW  = wU1 - wU0 + 1;
    const int nHW = nH * nW;
    const int R   = 3 * nHW;

    // stage K,V head slices: R rows x 6 uint4 each
    for (int idx = tid; idx < R * 6; idx += 256) {
        const int r  = idx / 6;
        const int ch = idx - r * 6;
        const int f   = r / nHW;
        const int rem = r - f * nHW;
        const int hh  = hU0 + rem / nW;
        const int ww  = wU0 + rem % nW;
        const int grow = ((b * T_FR + st + f) * HW + hh) * HW + ww;
        const __nv_bfloat16* base = qkvb + (size_t)grow * (3 * DH) + head * HDIM;
        ((uint4*)(s_k + r * AKSTR))[ch] = ((const uint4*)(base + DH))[ch];
        ((uint4*)(s_v + r * AKSTR))[ch] = ((const uint4*)(base + 2 * DH))[ch];
    }

    // stage q head slice (scaled fp32): 16 x 48
    const float scale = 0.144337567297406f;   // 48^-0.5
    for (int idx = tid; idx < 16 * HDIM; idx += 256) {
        const int i = idx / HDIM, j = idx - i * HDIM;
        const int hh = h0 + (i >> 2), ww = w0 + (i & 3);
        const int grow = ((b * T_FR + t) * HW + hh) * HW + ww;
        s_q[idx] = __bfloat162float(qkvb[(size_t)grow * (3 * DH) + head * HDIM + j]) * scale;
    }

    // neighbor-row table (head-independent)
    for (int idx = tid; idx < 16 * KCUBE; idx += 256) {
        const int i = idx / KCUBE, nb = idx - i * KCUBE;
        const int kt = nb / 9, kh = (nb / 3) % 3, kw = nb % 3;
        const int hh = h0 + (i >> 2), ww = w0 + (i & 3);
        const int sh = min(max(hh - 1, 0), HW - 3);
        const int sw = min(max(ww - 1, 0), HW - 3);
        s_r[idx] = (kt * nH + (sh + kh - hU0)) * nW + (sw + kw - wU0);
    }
    __syncthreads();

    // scores + bias: 16 x 27
    for (int idx = tid; idx < 16 * KCUBE; idx += 256) {
        const int i = idx / KCUBE, nb = idx - i * KCUBE;
        const int r = s_r[idx];
        const __nv_bfloat16* kp = s_k + r * AKSTR;
        const float* qp = s_q + i * HDIM;
        float s = 0.f;
        #pragma unroll
        for (int j = 0; j < HDIM; j++)
            s = fmaf(qp[j], __bfloat162float(kp[j]), s);
        const int kt = nb / 9, kh = (nb / 3) % 3, kw = nb % 3;
        const int hh = h0 + (i >> 2), ww = w0 + (i & 3);
        const int sh = min(max(hh - 1, 0), HW - 3);
        const int sw = min(max(ww - 1, 0), HW - 3);
        const int rt = st + kt - t + 2;
        const int rh = sh + kh - hh + 2;
        const int rw = sw + kw - ww + 2;
        s += rpb[((head * 5 + rt) * 5 + rh) * 5 + rw];
        s_p[idx] = s;
    }
    __syncthreads();

    // softmax: one thread per token row (serial over 27, same order as before)
    if (tid < 16) {
        float* pp = s_p + tid * KCUBE;
        float mx = -1e30f;
        #pragma unroll
        for (int k = 0; k < KCUBE; k++) mx = fmaxf(mx, pp[k]);
        float sum = 0.f;
        #pragma unroll
        for (int k = 0; k < KCUBE; k++) { float e = __expf(pp[k] - mx); pp[k] = e; sum += e; }
        const float inv = 1.0f / sum;
        #pragma unroll
        for (int k = 0; k < KCUBE; k++) pp[k] *= inv;
    }
    __syncthreads();

    // output: 16 x 48
    for (int idx = tid; idx < 16 * HDIM; idx += 256) {
        const int i = idx / HDIM, c = idx - i * HDIM;
        const float* pp = s_p + i * KCUBE;
        const int*   rt = s_r + i * KCUBE;
        float o = 0.f;
        #pragma unroll
        for (int nb = 0; nb < KCUBE; nb++)
            o = fmaf(pp[nb], __bfloat162float(s_v[rt[nb] * AKSTR + c]), o);
        const int hh = h0 + (i >> 2), ww = w0 + (i & 3);
        const int grow = ((b * T_FR + t) * HW + hh) * HW + ww;
        att[(size_t)grow * DH + head * HDIM + c] = __float2bfloat16(o);
    }
}

// ---------------- launch ----------------
extern "C" void kernel_launch(void* const* d_in, const int* in_sizes, int n_in,
                              void* d_out, int out_size)
{
    const float* x       = (const float*)d_in[0];
    const float* fc1_w   = (const float*)d_in[1];
    const float* fc1_b   = (const float*)d_in[2];
    const float* convA_w = (const float*)d_in[3];
    const float* convA_b = (const float*)d_in[4];
    const float* convB_w = (const float*)d_in[5];
    const float* convB_b = (const float*)d_in[6];
    const float* ln_g    = (const float*)d_in[7];
    const float* ln_b    = (const float*)d_in[8];
    const float* qkv_w   = (const float*)d_in[9];
    const float* qkv_b   = (const float*)d_in[10];
    const float* rpb     = (const float*)d_in[11];
    const float* proj_w  = (const float*)d_in[12];
    const float* proj_b  = (const float*)d_in[13];
    const float* fc2_w   = (const float*)d_in[14];
    const float* fc2_b   = (const float*)d_in[15];
    float* out = (float*)d_out;

    float *t1, *xs, *bconv;
    __nv_bfloat16 *xb, *t1b, *xsb, *yb, *qkvb, *attb;
    __nv_bfloat16 *wfc1, *wconv, *wqkv, *wproj, *wfc2;
    cudaGetSymbolAddress((void**)&t1,    g_t1);
    cudaGetSymbolAddress((void**)&xs,    g_xs);
    cudaGetSymbolAddress((void**)&bconv, g_b_conv);
    cudaGetSymbolAddress((void**)&xb,    g_xb);
    cudaGetSymbolAddress((void**)&t1b,   g_t1b);
    cudaGetSymbolAddress((void**)&xsb,   g_xsb);
    cudaGetSymbolAddress((void**)&yb,    g_yb);
    cudaGetSymbolAddress((void**)&qkvb,  g_qkvb);
    cudaGetSymbolAddress((void**)&attb,  g_attb);
    cudaGetSymbolAddress((void**)&wfc1,  g_w_fc1);
    cudaGetSymbolAddress((void**)&wconv, g_w_conv);
    cudaGetSymbolAddress((void**)&wqkv,  g_w_qkv);
    cudaGetSymbolAddress((void**)&wproj, g_w_proj);
    cudaGetSymbolAddress((void**)&wfc2,  g_w_fc2);

    cudaFuncSetAttribute(tc_gemm_k192<1, true, true>,
                         cudaFuncAttributeMaxDynamicSharedMemorySize, SMEM_G192);
    cudaFuncSetAttribute(tc_gemm_k192<2, false, true>,
                         cudaFuncAttributeMaxDynamicSharedMemorySize, SMEM_G192);

    const int gyA = (M_ALL + 127) / 128;   // 129
    const int gyP = M_PAT / 128;           // 128

    // 0) x conversion + weight prep, single launch
    prep_kernel<<<1024, 256>>>(x, fc1_w, qkv_w, proj_w, fc2_w,
                               convA_w, convA_b, convB_w, convB_b);
    // 1) fc1 (K=768, pipelined) -> t1 (f32) + t1b (bf16)
    tc_gemm<0, true, true><<<dim3(3, gyA), 256>>>(xb, wfc1, fc1_b, t1, t1b,
                                                  M_ALL, DH, D_MOD, nullptr);
    // 2) fused conv (K=192, single-shot): gelu(t1 + t1b@Mc^T + b') -> xs + xsb
    tc_gemm_k192<1, true, true><<<dim3(3, gyA), 256, SMEM_G192>>>(
        t1b, wconv, bconv, xs, xsb, M_ALL, DH, t1);
    // 3) LayerNorm -> yb (bf16)
    ln_warp<<<M_PAT / 8, 256>>>(xs, ln_g, ln_b, yb);
    // 4) qkv (K=192, pipelined) -> qkvb
    tc_gemm<0, false, true><<<dim3(9, gyP), 256>>>(yb, wqkv, qkv_b, nullptr, qkvb,
                                                   M_PAT, 3 * DH, DH, nullptr);
    // 5) per-(tile, head) attention -> attb (bf16)
    attn_head<<<BATCH * T_FR * 16 * HEADS, 256>>>(qkvb, rpb, attb);
    // 6) proj (K=192, single-shot): xsb[rr] = xs[rr] + proj(attb) + b
    tc_gemm_k192<2, false, true><<<dim3(3, gyP), 256, SMEM_G192>>>(
        attb, wproj, proj_b, nullptr, xsb, M_PAT, DH, xs);
    // 7) fc2 (K=192, pipelined) + outer residual(x) -> out (f32)
    tc_gemm<3, true, false><<<dim3(12, gyA), 256>>>(xsb, wfc2, fc2_b, out, nullptr,
                                                    M_ALL, D_MOD, DH, x);
}

// round 16
// speedup vs baseline: 1.0654x; 1.0168x over previous
#include <cuda_runtime.h>
#include <cuda_bf16.h>
#include <math.h>
#include <stdint.h>

// ---------------- problem constants ----------------
#define T_FR   8
#define N_TOK  257
#define HW     16
#define BATCH  8
#define D_MOD  768
#define DH     192
#define HEADS  4
#define HDIM   48
#define M_ALL  (T_FR * BATCH * N_TOK)   // 16448
#define M_PAT  (BATCH * T_FR * HW * HW) // 16384
#define KCUBE  27

// ---------------- scratch (bf16 intermediates only) ----------------
__device__ __nv_bfloat16 g_xb  [M_ALL * D_MOD];
__device__ __nv_bfloat16 g_t1b [M_ALL * DH];
__device__ __nv_bfloat16 g_xsb [M_ALL * DH];
__device__ __nv_bfloat16 g_yb  [M_PAT * DH];
__device__ __nv_bfloat16 g_qkvb[M_PAT * 3 * DH];
__device__ __nv_bfloat16 g_attb[M_PAT * DH];

__device__ __nv_bfloat16 g_w_fc1 [DH * D_MOD];
__device__ __nv_bfloat16 g_w_conv[DH * DH];
__device__ float         g_b_conv[DH];
__device__ __nv_bfloat16 g_w_qkv [3 * DH * DH];
__device__ __nv_bfloat16 g_w_proj[DH * DH];
__device__ __nv_bfloat16 g_w_fc2 [D_MOD * DH];

// ---------------- helpers ----------------
__device__ __forceinline__ float gelu_exact(float v) {
    return 0.5f * v * (1.0f + erff(v * 0.70710678118654752f));
}

__device__ __forceinline__ int patch_to_xs_row(int pr) {
    int b = pr >> 11;
    int t = (pr >> 8) & 7;
    int h = (pr >> 4) & 15;
    int w = pr & 15;
    return t * (BATCH * N_TOK) + b * N_TOK + 1 + (h << 4) + w;
}

__device__ __forceinline__ uint32_t pack_bf2(float lo, float hi) {
    uint32_t r;
    asm("cvt.rn.bf16x2.f32 %0, %1, %2;" : "=r"(r) : "f"(hi), "f"(lo));
    return r;
}

__device__ __forceinline__ float2 unpack_bf2(uint32_t u) {
    __nv_bfloat162 h = *(__nv_bfloat162*)&u;
    float2 f;
    f.x = __bfloat162float(h.x);
    f.y = __bfloat162float(h.y);
    return f;
}

__device__ __forceinline__ uint32_t smem_u32(const void* p) {
    uint32_t a;
    asm("{ .reg .u64 t; cvta.to.shared.u64 t, %1; cvt.u32.u64 %0, t; }"
        : "=r"(a) : "l"(p));
    return a;
}

#define CP16(dst, src) \
    asm volatile("cp.async.cg.shared.global [%0], [%1], 16;" \
        :: "r"(dst), "l"(src) : "memory")
#define CP_COMMIT() asm volatile("cp.async.commit_group;" ::: "memory")
#define CP_WAIT(N)  asm volatile("cp.async.wait_group %0;" :: "n"(N) : "memory")

#define LDSM4(r0, r1, r2, r3, addr) \
    asm volatile("ldmatrix.sync.aligned.m8n8.x4.shared.b16 {%0,%1,%2,%3}, [%4];" \
        : "=r"(r0), "=r"(r1), "=r"(r2), "=r"(r3) : "r"(addr))

#define MMA16816(cc, A0, A1, A2, A3, B0, B1) \
    asm volatile("mma.sync.aligned.m16n8k16.row.col.f32.bf16.bf16.f32 " \
        "{%0,%1,%2,%3}, {%4,%5,%6,%7}, {%8,%9}, {%0,%1,%2,%3};" \
        : "+f"((cc)[0]), "+f"((cc)[1]), "+f"((cc)[2]), "+f"((cc)[3]) \
        : "r"(A0), "r"(A1), "r"(A2), "r"(A3), "r"(B0), "r"(B1))

// shared epilogue
// MODE 0: v ; 1: gelu(resb[m]+v) ; 2: resb[rr]+v stored at rr (in-place ok) ;
// MODE 3: resf[m]+v
template <int MODE, bool WF32, bool WBF16>
__device__ __forceinline__ void gemm_epilogue(
    float acc[2][4][4], const float* __restrict__ bias,
    float* __restrict__ Cf, __nv_bfloat16* __restrict__ Cb,
    const float* __restrict__ resf, const __nv_bfloat16* __restrict__ resb,
    int m0, int n0, int wm, int wn, int lane, int M, int N)
{
    const int r  = lane >> 2;
    const int c2 = (lane & 3) * 2;
    #pragma unroll
    for (int mi = 0; mi < 2; mi++) {
        #pragma unroll
        for (int half = 0; half < 2; half++) {
            const int m = m0 + wm + mi * 16 + r + half * 8;
            if (m >= M) continue;
            const int orow = (MODE == 2) ? patch_to_xs_row(m) : m;
            #pragma unroll
            for (int nj = 0; nj < 4; nj++) {
                const int n = n0 + wn + nj * 8 + c2;
                float v0 = acc[mi][nj][half * 2 + 0] + bias[n];
                float v1 = acc[mi][nj][half * 2 + 1] + bias[n + 1];
                if (MODE == 1) {
                    const float2 rv = unpack_bf2(*(const uint32_t*)(resb + (size_t)m * N + n));
                    v0 = gelu_exact(rv.x + v0);
                    v1 = gelu_exact(rv.y + v1);
                } else if (MODE == 2) {
                    const float2 rv = unpack_bf2(*(const uint32_t*)(resb + (size_t)orow * N + n));
                    v0 += rv.x; v1 += rv.y;
                } else if (MODE == 3) {
                    const float2 rv = *(const float2*)(resf + (size_t)m * N + n);
                    v0 += rv.x; v1 += rv.y;
                }
                if (WF32) {
                    float2 o; o.x = v0; o.y = v1;
                    *(float2*)(Cf + (size_t)orow * N + n) = o;
                }
                if (WBF16) {
                    *(uint32_t*)(Cb + (size_t)orow * N + n) = pack_bf2(v0, v1);
                }
            }
        }
    }
}

// ---------------- pipelined bf16 GEMM (fc1/qkv/fc2) ----------------
#define ASTRIDE 80
#define A_ST (128 * ASTRIDE)
#define B_ST (64 * ASTRIDE)
#define STAGE (A_ST + B_ST)
#define NSTG 3

template <int MODE, bool WF32, bool WBF16>
__global__ __launch_bounds__(256)
void tc_gemm(const __nv_bfloat16* __restrict__ A,
             const __nv_bfloat16* __restrict__ W,
             const float* __restrict__ bias,
             float* __restrict__ Cf,
             __nv_bfloat16* __restrict__ Cb,
             int M, int N, int Kc,
             const float* __restrict__ resf,
             const __nv_bfloat16* __restrict__ resb)
{
    __shared__ __align__(128) uint8_t smem[NSTG * STAGE];

    const int tid    = threadIdx.x;
    const int warpid = tid >> 5;
    const int lane   = tid & 31;
    const int m0     = blockIdx.y * 128;
    const int n0     = blockIdx.x * 64;

    const int wm = (warpid >> 1) * 32;
    const int wn = (warpid & 1) * 32;

    const uint32_t sbase = smem_u32(smem);

    const int r4 = tid >> 2;
    const int c4 = tid & 3;
    const int rowA0 = min(m0 + r4, M - 1);
    const int rowA1 = min(m0 + 64 + r4, M - 1);
    const __nv_bfloat16* Ap0 = A + (size_t)rowA0 * Kc + c4 * 8;
    const __nv_bfloat16* Ap1 = A + (size_t)rowA1 * Kc + c4 * 8;
    const __nv_bfloat16* Bp  = W + (size_t)(n0 + r4) * Kc + c4 * 8;
    const uint32_t dA0 = (uint32_t)(r4 * ASTRIDE + c4 * 16);
    const uint32_t dA1 = (uint32_t)((64 + r4) * ASTRIDE + c4 * 16);
    const uint32_t dB  = (uint32_t)(A_ST + r4 * ASTRIDE + c4 * 16);

    const int l8  = lane & 7;
    const int mtx = lane >> 3;
    const uint32_t aoff = (uint32_t)((wm + (mtx & 1) * 8 + l8) * ASTRIDE + (mtx >> 1) * 16);
    const uint32_t boff = (uint32_t)(A_ST + (wn + (mtx >> 1) * 8 + l8) * ASTRIDE + (mtx & 1) * 16);

    float acc[2][4][4];
    #pragma unroll
    for (int i = 0; i < 2; i++)
        #pragma unroll
        for (int j = 0; j < 4; j++)
            #pragma unroll
            for (int q = 0; q < 4; q++) acc[i][j][q] = 0.f;

    const int KT = Kc / 32;

    #pragma unroll
    for (int s = 0; s < 2; s++) {
        if (s < KT) {
            uint32_t b = sbase + s * STAGE;
            const int ko = s * 32;
            CP16(b + dA0, Ap0 + ko);
            CP16(b + dA1, Ap1 + ko);
            CP16(b + dB,  Bp  + ko);
            CP_COMMIT();
        }
    }

    int buf = 0;
    for (int kt = 0; kt < KT; kt++) {
        if (kt + 1 < KT) { CP_WAIT(1); } else { CP_WAIT(0); }
        __syncthreads();

        if (kt + 2 < KT) {
            int nb = buf + 2; if (nb >= NSTG) nb -= NSTG;
            uint32_t b = sbase + nb * STAGE;
            const int ko = (kt + 2) * 32;
            CP16(b + dA0, Ap0 + ko);
            CP16(b + dA1, Ap1 + ko);
            CP16(b + dB,  Bp  + ko);
            CP_COMMIT();
        }

        const uint32_t abase = sbase + buf * STAGE + aoff;
        const uint32_t bbase = sbase + buf * STAGE + boff;

        #pragma unroll
        for (int ks = 0; ks < 2; ks++) {
            uint32_t a0[4], a1[4], b0[4], b1[4];
            LDSM4(a0[0], a0[1], a0[2], a0[3], abase + ks * 32);
            LDSM4(a1[0], a1[1], a1[2], a1[3], abase + 16 * ASTRIDE + ks * 32);
            LDSM4(b0[0], b0[1], b0[2], b0[3], bbase + ks * 32);
            LDSM4(b1[0], b1[1], b1[2], b1[3], bbase + 16 * ASTRIDE + ks * 32);

            MMA16816(acc[0][0], a0[0], a0[1], a0[2], a0[3], b0[0], b0[1]);
            MMA16816(acc[0][1], a0[0], a0[1], a0[2], a0[3], b0[2], b0[3]);
            MMA16816(acc[0][2], a0[0], a0[1], a0[2], a0[3], b1[0], b1[1]);
            MMA16816(acc[0][3], a0[0], a0[1], a0[2], a0[3], b1[2], b1[3]);
            MMA16816(acc[1][0], a1[0], a1[1], a1[2], a1[3], b0[0], b0[1]);
            MMA16816(acc[1][1], a1[0], a1[1], a1[2], a1[3], b0[2], b0[3]);
            MMA16816(acc[1][2], a1[0], a1[1], a1[2], a1[3], b1[0], b1[1]);
            MMA16816(acc[1][3], a1[0], a1[1], a1[2], a1[3], b1[2], b1[3]);
        }

        if (++buf == NSTG) buf = 0;
    }

    gemm_epilogue<MODE, WF32, WBF16>(acc, bias, Cf, Cb, resf, resb,
                                     m0, n0, wm, wn, lane, M, N);
}

// ---------------- single-shot K=192 GEMM, XOR-swizzled (conv/proj) ----------------
#define KSTRB 384
#define A192  (128 * KSTRB)
#define SMEM_G192 (A192 + 64 * KSTRB)    // 73728

template <int MODE, bool WF32, bool WBF16>
__global__ __launch_bounds__(256)
void tc_gemm_k192(const __nv_bfloat16* __restrict__ A,
                  const __nv_bfloat16* __restrict__ W,
                  const float* __restrict__ bias,
                  float* __restrict__ Cf,
                  __nv_bfloat16* __restrict__ Cb,
                  int M, int N,
                  const float* __restrict__ resf,
                  const __nv_bfloat16* __restrict__ resb)
{
    extern __shared__ __align__(128) uint8_t dsm[];

    const int tid    = threadIdx.x;
    const int warpid = tid >> 5;
    const int lane   = tid & 31;
    const int m0     = blockIdx.y * 128;
    const int n0     = blockIdx.x * 64;
    const int Kc     = 192;

    const int wm = (warpid >> 1) * 32;
    const int wn = (warpid & 1) * 32;

    const uint32_t sbase = smem_u32(dsm);

    #pragma unroll
    for (int i = 0; i < 12; i++) {
        const int idx = tid + 256 * i;
        const int row = idx / 24, ch = idx % 24;
        const int grow = min(m0 + row, M - 1);
        CP16(sbase + (uint32_t)(row * KSTRB + ((ch ^ (row & 7)) << 4)),
             A + (size_t)grow * Kc + ch * 8);
    }
    #pragma unroll
    for (int i = 0; i < 6; i++) {
        const int idx = tid + 256 * i;
        const int row = idx / 24, ch = idx % 24;
        CP16(sbase + (uint32_t)(A192 + row * KSTRB + ((ch ^ (row & 7)) << 4)),
             W + (size_t)(n0 + row) * Kc + ch * 8);
    }
    CP_COMMIT();

    const int l8  = lane & 7;
    const int mtx = lane >> 3;
    const uint32_t arow0 = sbase + (uint32_t)((wm + (mtx & 1) * 8 + l8) * KSTRB);
    const uint32_t brow0 = sbase + (uint32_t)(A192 + (wn + (mtx >> 1) * 8 + l8) * KSTRB);
    const int ca = mtx >> 1;
    const int cb = mtx & 1;
    const int msk = l8;

    float acc[2][4][4];
    #pragma unroll
    for (int i = 0; i < 2; i++)
        #pragma unroll
        for (int j = 0; j < 4; j++)
            #pragma unroll
            for (int q = 0; q < 4; q++) acc[i][j][q] = 0.f;

    CP_WAIT(0);
    __syncthreads();

    #pragma unroll
    for (int ks = 0; ks < 12; ks++) {
        const uint32_t sa = (uint32_t)(((ca + 2 * ks) ^ msk) << 4);
        const uint32_t sb = (uint32_t)(((cb + 2 * ks) ^ msk) << 4);
        uint32_t a0[4], a1[4], b0[4], b1[4];
        LDSM4(a0[0], a0[1], a0[2], a0[3], arow0 + sa);
        LDSM4(a1[0], a1[1], a1[2], a1[3], arow0 + 16 * KSTRB + sa);
        LDSM4(b0[0], b0[1], b0[2], b0[3], brow0 + sb);
        LDSM4(b1[0], b1[1], b1[2], b1[3], brow0 + 16 * KSTRB + sb);

        MMA16816(acc[0][0], a0[0], a0[1], a0[2], a0[3], b0[0], b0[1]);
        MMA16816(acc[0][1], a0[0], a0[1], a0[2], a0[3], b0[2], b0[3]);
        MMA16816(acc[0][2], a0[0], a0[1], a0[2], a0[3], b1[0], b1[1]);
        MMA16816(acc[0][3], a0[0], a0[1], a0[2], a0[3], b1[2], b1[3]);
        MMA16816(acc[1][0], a1[0], a1[1], a1[2], a1[3], b0[0], b0[1]);
        MMA16816(acc[1][1], a1[0], a1[1], a1[2], a1[3], b0[2], b0[3]);
        MMA16816(acc[1][2], a1[0], a1[1], a1[2], a1[3], b1[0], b1[1]);
        MMA16816(acc[1][3], a1[0], a1[1], a1[2], a1[3], b1[2], b1[3]);
    }

    gemm_epilogue<MODE, WF32, WBF16>(acc, bias, Cf, Cb, resf, resb,
                                     m0, n0, wm, wn, lane, M, N);
}

// ---------------- prep: x->bf16 + weight conversions + conv fold ----------------
__global__ void prep_kernel(const float* __restrict__ x,
                            const float* s0, const float* s3,
                            const float* s4, const float* s5,
                            const float* cA, const float* cAb,
                            const float* cB, const float* cBb)
{
    const int stride = gridDim.x * blockDim.x;
    const int t = blockIdx.x * blockDim.x + threadIdx.x;

    const int n4 = (M_ALL * D_MOD) / 4;
    for (int i = t; i < n4; i += stride) {
        float4 v = *(const float4*)(x + 4 * (size_t)i);
        uint2 o;
        o.x = pack_bf2(v.x, v.y);
        o.y = pack_bf2(v.z, v.w);
        *(uint2*)((uint16_t*)g_xb + 4 * (size_t)i) = o;
    }

    for (int i = t; i < DH * D_MOD;   i += stride) g_w_fc1[i]  = __float2bfloat16(s0[i]);
    for (int i = t; i < 3 * DH * DH;  i += stride) g_w_qkv[i]  = __float2bfloat16(s3[i]);
    for (int i = t; i < DH * DH;      i += stride) g_w_proj[i] = __float2bfloat16(s4[i]);
    for (int i = t; i < D_MOD * DH;   i += stride) g_w_fc2[i]  = __float2bfloat16(s5[i]);
    for (int idx = t; idx < DH * DH; idx += stride) {
        const int i = idx / DH, j = idx % DH;
        float s = 0.f;
        #pragma unroll 8
        for (int k = 0; k < 64; k++)
            s = fmaf(cB[i * 64 + k], cA[k * DH + j], s);
        g_w_conv[idx] = __float2bfloat16(s);
    }
    for (int i = t; i < DH; i += stride) {
        float s = cBb[i];
        for (int k = 0; k < 64; k++)
            s = fmaf(cB[i * 64 + k], cAb[k], s);
        g_b_conv[i] = s;
    }
}

// ---------------- LayerNorm: warp-per-row (bf16 in, bf16 out) ----------------
__global__ __launch_bounds__(256)
void ln_warp(const __nv_bfloat16* __restrict__ xsb,
             const float* __restrict__ gamma,
             const float* __restrict__ beta,
             __nv_bfloat16* __restrict__ y)
{
    const int wid  = threadIdx.x >> 5;
    const int lane = threadIdx.x & 31;
    const int pr   = blockIdx.x * 8 + wid;
    const int row  = patch_to_xs_row(pr);

    // 192 bf16 per row = 96 u32; lane loads 3 u32 (stride 32) = 6 values
    const uint32_t* src = (const uint32_t*)(xsb + (size_t)row * DH);
    float v[6];
    float s = 0.f;
    #pragma unroll
    for (int k = 0; k < 3; k++) {
        const float2 p = unpack_bf2(src[lane + 32 * k]);
        v[2 * k] = p.x; v[2 * k + 1] = p.y;
        s += p.x + p.y;
    }
    #pragma unroll
    for (int o = 16; o > 0; o >>= 1) s += __shfl_xor_sync(0xffffffff, s, o);
    const float mu = s * (1.0f / DH);

    float s2 = 0.f;
    #pragma unroll
    for (int k = 0; k < 6; k++) { v[k] -= mu; s2 += v[k] * v[k]; }
    #pragma unroll
    for (int o = 16; o > 0; o >>= 1) s2 += __shfl_xor_sync(0xffffffff, s2, o);
    const float inv = rsqrtf(s2 * (1.0f / DH) + 1e-5f);

    uint32_t* dst = (uint32_t*)(y + (size_t)pr * DH);
    #pragma unroll
    for (int k = 0; k < 3; k++) {
        const int c = 2 * (lane + 32 * k);
        const float y0 = v[2 * k]     * inv * gamma[c]     + beta[c];
        const float y1 = v[2 * k + 1] * inv * gamma[c + 1] + beta[c + 1];
        dst[lane + 32 * k] = pack_bf2(y0, y1);
    }
}

// ---------------- per-(tile, head) 3D neighborhood attention ----------------
#define RMAX  108
#define AKSTR 56   // bf16 per row (48 + 8 pad)

__global__ __launch_bounds__(256)
void attn_head(const __nv_bfloat16* __restrict__ qkvb,
               const float* __restrict__ rpb,
               __nv_bfloat16* __restrict__ att)
{
    __shared__ __nv_bfloat16 s_k[RMAX * AKSTR];
    __shared__ __nv_bfloat16 s_v[RMAX * AKSTR];
    __shared__ float s_q[16 * HDIM];
    __shared__ float s_p[16 * KCUBE];
    __shared__ int   s_r[16 * KCUBE];

    const int tid = threadIdx.x;

    int bid = blockIdx.x;
    const int head = bid & 3;  bid >>= 2;
    const int tw   = bid & 3;  bid >>= 2;
    const int th   = bid & 3;  bid >>= 2;
    const int t    = bid & 7;  bid >>= 3;
    const int b    = bid;
    const int h0 = th * 4, w0 = tw * 4;

    const int st  = min(max(t - 1, 0), T_FR - 3);
    const int hU0 = max(h0 - 1, 0), hU1 = min(h0 + 4, 15);
    const int wU0 = max(w0 - 1, 0), wU1 = min(w0 + 4, 15);
    const int nH  = hU1 - hU0 + 1;
    const int nW  = wU1 - wU0 + 1;
    const int nHW = nH * nW;
    const int R   = 3 * nHW;

    for (int idx = tid; idx < R * 6; idx += 256) {
        const int r  = idx / 6;
        const int ch = idx - r * 6;
        const int f   = r / nHW;
        const int rem = r - f * nHW;
        const int hh  = hU0 + rem / nW;
        const int ww  = wU0 + rem % nW;
        const int grow = ((b * T_FR + st + f) * HW + hh) * HW + ww;
        const __nv_bfloat16* base = qkvb + (size_t)grow * (3 * DH) + head * HDIM;
        ((uint4*)(s_k + r * AKSTR))[ch] = ((const uint4*)(base + DH))[ch];
        ((uint4*)(s_v + r * AKSTR))[ch] = ((const uint4*)(base + 2 * DH))[ch];
    }

    const float scale = 0.144337567297406f;   // 48^-0.5
    for (int idx = tid; idx < 16 * HDIM; idx += 256) {
        const int i = idx / HDIM, j = idx - i * HDIM;
        const int hh = h0 + (i >> 2), ww = w0 + (i & 3);
        const int grow = ((b * T_FR + t) * HW + hh) * HW + ww;
        s_q[idx] = __bfloat162float(qkvb[(size_t)grow * (3 * DH) + head * HDIM + j]) * scale;
    }

    for (int idx = tid; idx < 16 * KCUBE; idx += 256) {
        const int i = idx / KCUBE, nb = idx - i * KCUBE;
        const int kt = nb / 9, kh = (nb / 3) % 3, kw = nb % 3;
        const int hh = h0 + (i >> 2), ww = w0 + (i & 3);
        const int sh = min(max(hh - 1, 0), HW - 3);
        const int sw = min(max(ww - 1, 0), HW - 3);
        s_r[idx] = (kt * nH + (sh + kh - hU0)) * nW + (sw + kw - wU0);
    }
    __syncthreads();

    for (int idx = tid; idx < 16 * KCUBE; idx += 256) {
        const int i = idx / KCUBE, nb = idx - i * KCUBE;
        const int r = s_r[idx];
        const __nv_bfloat16* kp = s_k + r * AKSTR;
        const float* qp = s_q + i * HDIM;
        float s = 0.f;
        #pragma unroll
        for (int j = 0; j < HDIM; j++)
            s = fmaf(qp[j], __bfloat162float(kp[j]), s);
        const int kt = nb / 9, kh = (nb / 3) % 3, kw = nb % 3;
        const int hh = h0 + (i >> 2), ww = w0 + (i & 3);
        const int sh = min(max(hh - 1, 0), HW - 3);
        const int sw = min(max(ww - 1, 0), HW - 3);
        const int rt = st + kt - t + 2;
        const int rh = sh + kh - hh + 2;
        const int rw = sw + kw - ww + 2;
        s += rpb[((head * 5 + rt) * 5 + rh) * 5 + rw];
        s_p[idx] = s;
    }
    __syncthreads();

    if (tid < 16) {
        float* pp = s_p + tid * KCUBE;
        float mx = -1e30f;
        #pragma unroll
        for (int k = 0; k < KCUBE; k++) mx = fmaxf(mx, pp[k]);
        float sum = 0.f;
        #pragma unroll
        for (int k = 0; k < KCUBE; k++) { float e = __expf(pp[k] - mx); pp[k] = e; sum += e; }
        const float inv = 1.0f / sum;
        #pragma unroll
        for (int k = 0; k < KCUBE; k++) pp[k] *= inv;
    }
    __syncthreads();

    for (int idx = tid; idx < 16 * HDIM; idx += 256) {
        const int i = idx / HDIM, c = idx - i * HDIM;
        const float* pp = s_p + i * KCUBE;
        const int*   rt = s_r + i * KCUBE;
        float o = 0.f;
        #pragma unroll
        for (int nb = 0; nb < KCUBE; nb++)
            o = fmaf(pp[nb], __bfloat162float(s_v[rt[nb] * AKSTR + c]), o);
        const int hh = h0 + (i >> 2), ww = w0 + (i & 3);
        const int grow = ((b * T_FR + t) * HW + hh) * HW + ww;
        att[(size_t)grow * DH + head * HDIM + c] = __float2bfloat16(o);
    }
}

// ---------------- launch ----------------
extern "C" void kernel_launch(void* const* d_in, const int* in_sizes, int n_in,
                              void* d_out, int out_size)
{
    const float* x       = (const float*)d_in[0];
    const float* fc1_w   = (const float*)d_in[1];
    const float* fc1_b   = (const float*)d_in[2];
    const float* convA_w = (const float*)d_in[3];
    const float* convA_b = (const float*)d_in[4];
    const float* convB_w = (const float*)d_in[5];
    const float* convB_b = (const float*)d_in[6];
    const float* ln_g    = (const float*)d_in[7];
    const float* ln_b    = (const float*)d_in[8];
    const float* qkv_w   = (const float*)d_in[9];
    const float* qkv_b   = (const float*)d_in[10];
    const float* rpb     = (const float*)d_in[11];
    const float* proj_w  = (const float*)d_in[12];
    const float* proj_b  = (const float*)d_in[13];
    const float* fc2_w   = (const float*)d_in[14];
    const float* fc2_b   = (const float*)d_in[15];
    float* out = (float*)d_out;

    float *bconv;
    __nv_bfloat16 *xb, *t1b, *xsb, *yb, *qkvb, *attb;
    __nv_bfloat16 *wfc1, *wconv, *wqkv, *wproj, *wfc2;
    cudaGetSymbolAddress((void**)&bconv, g_b_conv);
    cudaGetSymbolAddress((void**)&xb,    g_xb);
    cudaGetSymbolAddress((void**)&t1b,   g_t1b);
    cudaGetSymbolAddress((void**)&xsb,   g_xsb);
    cudaGetSymbolAddress((void**)&yb,    g_yb);
    cudaGetSymbolAddress((void**)&qkvb,  g_qkvb);
    cudaGetSymbolAddress((void**)&attb,  g_attb);
    cudaGetSymbolAddress((void**)&wfc1,  g_w_fc1);
    cudaGetSymbolAddress((void**)&wconv, g_w_conv);
    cudaGetSymbolAddress((void**)&wqkv,  g_w_qkv);
    cudaGetSymbolAddress((void**)&wproj, g_w_proj);
    cudaGetSymbolAddress((void**)&wfc2,  g_w_fc2);

    cudaFuncSetAttribute(tc_gemm_k192<1, false, true>,
                         cudaFuncAttributeMaxDynamicSharedMemorySize, SMEM_G192);
    cudaFuncSetAttribute(tc_gemm_k192<2, false, true>,
                         cudaFuncAttributeMaxDynamicSharedMemorySize, SMEM_G192);

    const int gyA = (M_ALL + 127) / 128;   // 129
    const int gyP = M_PAT / 128;           // 128

    // 0) x conversion + weight prep
    prep_kernel<<<1024, 256>>>(x, fc1_w, qkv_w, proj_w, fc2_w,
                               convA_w, convA_b, convB_w, convB_b);
    // 1) fc1 (K=768, pipelined) -> t1b (bf16 only)
    tc_gemm<0, false, true><<<dim3(3, gyA), 256>>>(xb, wfc1, fc1_b, nullptr, t1b,
                                                   M_ALL, DH, D_MOD, nullptr, nullptr);
    // 2) fused conv (K=192): gelu(t1b + t1b@Mc^T + b') -> xsb (bf16 only)
    tc_gemm_k192<1, false, true><<<dim3(3, gyA), 256, SMEM_G192>>>(
        t1b, wconv, bconv, nullptr, xsb, M_ALL, DH, nullptr, t1b);
    // 3) LayerNorm (bf16 in) -> yb (bf16)
    ln_warp<<<M_PAT / 8, 256>>>(xsb, ln_g, ln_b, yb);
    // 4) qkv (K=192, pipelined) -> qkvb
    tc_gemm<0, false, true><<<dim3(9, gyP), 256>>>(yb, wqkv, qkv_b, nullptr, qkvb,
                                                   M_PAT, 3 * DH, DH, nullptr, nullptr);
    // 5) per-(tile, head) attention -> attb (bf16)
    attn_head<<<BATCH * T_FR * 16 * HEADS, 256>>>(qkvb, rpb, attb);
    // 6) proj (K=192): xsb[rr] += proj(attb) + b  (in-place bf16 residual)
    tc_gemm_k192<2, false, true><<<dim3(3, gyP), 256, SMEM_G192>>>(
        attb, wproj, proj_b, nullptr, xsb, M_PAT, DH, nullptr, xsb);
    // 7) fc2 (K=192, pipelined) + outer residual(x, fp32) -> out (f32)
    tc_gemm<3, true, false><<<dim3(12, gyA), 256>>>(xsb, wfc2, fc2_b, out, nullptr,
                                                    M_ALL, D_MOD, DH, x, nullptr);
}